// round 12
// baseline (speedup 1.0000x reference)
#include <cuda_runtime.h>
#include <cstdint>
#include <cstddef>

#define B_ 256
#define S_ 512
#define H_ 512
#define V_ 128

// Scratch (allocation-free rule: __device__ globals)
__device__ float g_P[V_ * H_];                       // 256 KB: P[v][h] = emb[v]@W_ih + b_ih + b_hh
__device__ float g_H[(size_t)S_ * B_ * H_];          // 268 MB: hidden history [t][b][h] (for out_gemm)
__device__ float g_Ht2[2][8][H_][32];                // 2 MB ping-pong transposed h: [par][rowtile][col][row-in-tile]
__device__ unsigned g_cnt;                           // grid-barrier arrive counter
__device__ unsigned g_epoch;                         // grid-barrier epoch (monotonic across replays)

// ---- packed f32x2 helpers (sm_103a) ----
__device__ __forceinline__ unsigned long long pack2(float x, float y) {
    unsigned long long r;
    asm("mov.b64 %0, {%1, %2};" : "=l"(r) : "f"(x), "f"(y));
    return r;
}
__device__ __forceinline__ void unpack2(unsigned long long v, float& x, float& y) {
    asm("mov.b64 {%0, %1}, %2;" : "=f"(x), "=f"(y) : "l"(v));
}
#define FMA2(acc, a, b) \
    asm("fma.rn.f32x2 %0, %1, %2, %3;" : "=l"(acc) : "l"(a), "l"(b), "l"(acc))

// ============================================================
// Kernel 1: P[v][h] = emb[v] @ W_ih + b_ih + b_hh
// ============================================================
__global__ void precompute_P(const float* __restrict__ emb,
                             const float* __restrict__ W_ih,
                             const float* __restrict__ b_ih,
                             const float* __restrict__ b_hh) {
    __shared__ float es[H_];
    const int v = blockIdx.x;
    const int h = threadIdx.x;
    es[h] = emb[v * H_ + h];
    __syncthreads();
    float acc = b_ih[h] + b_hh[h];
#pragma unroll 4
    for (int k = 0; k < H_; k++)
        acc = fmaf(es[k], W_ih[k * H_ + h], acc);
    g_P[v * H_ + h] = acc;
}

// ============================================================
// Kernel 2: PERSISTENT recurrence, row-pair accumulator scheme.
// grid = (16 col-tiles of 32, 8 row-tiles of 32) = 128 CTAs, 128 threads.
// SMEM: Wd[512][32] u64  = 128KB  (W_hh slice, each value duplicated {w,w})
//       hs[512][16] u64  =  64KB  (h_prev transposed: [k][16 row-pairs])
// Thread (t_r = tid&7, c2 = tid>>3) owns rows 4t_r..4t_r+3 (2 pairs),
// cols 2c2, 2c2+1. Inner loop: 2x LDS.128 + 4x fma.rn.f32x2.
// f32x2 lanes = adjacent batch rows => transposed h layout is free.
// ============================================================
__global__ __launch_bounds__(128) void rnn_persist(const float* __restrict__ Whh,
                                                   const int* __restrict__ x) {
    extern __shared__ char smem_raw[];
    unsigned long long* Wd = (unsigned long long*)smem_raw;            // [512][32]
    unsigned long long* hs = (unsigned long long*)(smem_raw + 131072); // [512][16]

    const int tid = threadIdx.x;
    const int bx = blockIdx.x;     // col tile 0..15 (32 cols)
    const int by = blockIdx.y;     // row tile 0..7  (32 rows)

    // ---- build duplicated W slice in SMEM (once) ----
#pragma unroll
    for (int it = 0; it < 64; it++) {
        int i = tid + it * 128;            // 0..8191 float2s
        int k = i >> 4;                    // 16 float2 per k-row
        int c = i & 15;
        float2 w = *(const float2*)(Whh + (size_t)k * H_ + bx * 32 + c * 2);
        Wd[k * 32 + c * 2 + 0] = pack2(w.x, w.x);
        Wd[k * 32 + c * 2 + 1] = pack2(w.y, w.y);
    }

    unsigned e0 = 0;
    if (tid == 0) e0 = *(volatile unsigned*)&g_epoch;   // epoch base (replay-safe)
    __syncthreads();

    const int t_r = tid & 7;       // row-pair group: rows 4t_r..4t_r+3
    const int c2  = tid >> 3;      // col pair: cols 2c2, 2c2+1
    const int gc  = bx * 32 + 2 * c2;            // global col of first col
    const int b0  = by * 32 + 4 * t_r;           // global row of first row

    const char* hb = (const char*)hs + t_r * 16;   // + k*128
    const char* wb = (const char*)Wd + c2 * 16;    // + k*256

    for (int t = 0; t < S_; t++) {
        unsigned long long a00 = 0ull, a01 = 0ull, a10 = 0ull, a11 = 0ull;
        // a00: rows(4t_r,4t_r+1) col gc    a01: rows(4t_r,4t_r+1) col gc+1
        // a10: rows(4t_r+2,+3)   col gc    a11: rows(4t_r+2,+3)   col gc+1

        if (t > 0) {
            // ---- stage h_prev: contiguous 64KB, coalesced, bypass L1 ----
            const float4* src = (const float4*)&g_Ht2[(t - 1) & 1][by][0][0];
            float4* dst = (float4*)hs;
#pragma unroll 8
            for (int it = 0; it < 32; it++) {
                int i = tid + it * 128;        // 0..4095 float4s
                dst[i] = __ldcg(src + i);
            }
            __syncthreads();

            // ---- FMA-bound mainloop ----
#pragma unroll 8
            for (int k = 0; k < H_; k++) {
                ulonglong2 hh = *(const ulonglong2*)(hb + (size_t)k * 128);
                ulonglong2 ww = *(const ulonglong2*)(wb + (size_t)k * 256);
                FMA2(a00, hh.x, ww.x);
                FMA2(a01, hh.x, ww.y);
                FMA2(a10, hh.y, ww.x);
                FMA2(a11, hh.y, ww.y);
            }
        }

        // ---- epilogue: + P[token], tanh, store (transposed + history) ----
        int xv0 = __ldg(&x[(b0 + 0) * S_ + t]);
        int xv1 = __ldg(&x[(b0 + 1) * S_ + t]);
        int xv2 = __ldg(&x[(b0 + 2) * S_ + t]);
        int xv3 = __ldg(&x[(b0 + 3) * S_ + t]);
        float2 p0 = *(const float2*)(g_P + (size_t)xv0 * H_ + gc);
        float2 p1 = *(const float2*)(g_P + (size_t)xv1 * H_ + gc);
        float2 p2 = *(const float2*)(g_P + (size_t)xv2 * H_ + gc);
        float2 p3 = *(const float2*)(g_P + (size_t)xv3 * H_ + gc);

        float s0, s1;
        float v00, v10, v20, v30, v01, v11, v21, v31;  // v{row i}{col j}
        unpack2(a00, s0, s1); v00 = tanhf(s0 + p0.x); v10 = tanhf(s1 + p1.x);
        unpack2(a01, s0, s1); v01 = tanhf(s0 + p0.y); v11 = tanhf(s1 + p1.y);
        unpack2(a10, s0, s1); v20 = tanhf(s0 + p2.x); v30 = tanhf(s1 + p3.x);
        unpack2(a11, s0, s1); v21 = tanhf(s0 + p2.y); v31 = tanhf(s1 + p3.y);

        // transposed ping-pong buffer: [t&1][by][col][row-pair u64]
        unsigned long long* td0 = (unsigned long long*)&g_Ht2[t & 1][by][gc + 0][0];
        unsigned long long* td1 = (unsigned long long*)&g_Ht2[t & 1][by][gc + 1][0];
        td0[2 * t_r + 0] = pack2(v00, v10);
        td0[2 * t_r + 1] = pack2(v20, v30);
        td1[2 * t_r + 0] = pack2(v01, v11);
        td1[2 * t_r + 1] = pack2(v21, v31);

        // history buffer [t][b][h] for out_gemm
        float* hh0 = g_H + (size_t)t * (B_ * H_) + (size_t)(b0 + 0) * H_ + gc;
        float* hh1 = g_H + (size_t)t * (B_ * H_) + (size_t)(b0 + 1) * H_ + gc;
        float* hh2 = g_H + (size_t)t * (B_ * H_) + (size_t)(b0 + 2) * H_ + gc;
        float* hh3 = g_H + (size_t)t * (B_ * H_) + (size_t)(b0 + 3) * H_ + gc;
        *(float2*)hh0 = make_float2(v00, v01);
        *(float2*)hh1 = make_float2(v10, v11);
        *(float2*)hh2 = make_float2(v20, v21);
        *(float2*)hh3 = make_float2(v30, v31);

        __syncthreads();   // hs no longer read; stores issued
        // ---- software grid barrier ----
        if (tid == 0) {
            __threadfence();                                // h visible in L2 before arrive
            unsigned old = atomicAdd(&g_cnt, 1);
            if (old == 127) {                               // last arriver
                atomicExch(&g_cnt, 0);
                __threadfence();
                atomicAdd(&g_epoch, 1);                     // release
            }
            while (*(volatile unsigned*)&g_epoch < e0 + (unsigned)(t + 1)) { }
        }
        __syncthreads();
    }
}

// ============================================================
// Kernel 3: output projection  out[b][s][v] = g_H[s][b] @ W_ho + b_o
// ============================================================
__global__ __launch_bounds__(256) void out_gemm(const float* __restrict__ Who,
                                                const float* __restrict__ b_o,
                                                float* __restrict__ out) {
    __shared__ unsigned long long Hs[128 * 16];  // duplicated pairs, 16 KB
    __shared__ float Ws[16 * 64];                // 4 KB

    const int tid = threadIdx.x;
    const int rb  = blockIdx.x;      // row block
    const int cb  = blockIdx.y;      // col block (0..1)
    const int tx  = tid & 7;         // 8 col groups of 8 cols
    const int ty  = tid >> 3;        // 32 row groups of 4 rows

    unsigned long long acc[4][4];
#pragma unroll
    for (int i = 0; i < 4; i++)
#pragma unroll
        for (int j = 0; j < 4; j++) acc[i][j] = 0ull;

    const float* Hbase = g_H + (size_t)rb * 128 * H_;

    for (int k0 = 0; k0 < H_; k0 += 16) {
        __syncthreads();
#pragma unroll
        for (int it = 0; it < 2; it++) {
            int fi = tid + it * 256;          // 0..511
            int row = fi >> 2, part = fi & 3;
            float4 v = *(const float4*)(Hbase + (size_t)row * H_ + k0 + part * 4);
            unsigned long long* d = Hs + row * 16 + part * 4;
            d[0] = pack2(v.x, v.x);
            d[1] = pack2(v.y, v.y);
            d[2] = pack2(v.z, v.z);
            d[3] = pack2(v.w, v.w);
        }
        {
            int fi = tid;                      // 0..255
            int kk = fi >> 4, part = fi & 15;
            float4 v = *(const float4*)(Who + (size_t)(k0 + kk) * V_ + cb * 64 + part * 4);
            *(float4*)(Ws + kk * 64 + part * 4) = v;
        }
        __syncthreads();

#pragma unroll
        for (int k = 0; k < 16; k++) {
            unsigned long long h0 = Hs[(ty * 4 + 0) * 16 + k];
            unsigned long long h1 = Hs[(ty * 4 + 1) * 16 + k];
            unsigned long long h2 = Hs[(ty * 4 + 2) * 16 + k];
            unsigned long long h3 = Hs[(ty * 4 + 3) * 16 + k];
            ulonglong2 w0 = *(const ulonglong2*)&Ws[k * 64 + tx * 8];
            ulonglong2 w1 = *(const ulonglong2*)&Ws[k * 64 + tx * 8 + 4];
            FMA2(acc[0][0], h0, w0.x); FMA2(acc[0][1], h0, w0.y);
            FMA2(acc[0][2], h0, w1.x); FMA2(acc[0][3], h0, w1.y);
            FMA2(acc[1][0], h1, w0.x); FMA2(acc[1][1], h1, w0.y);
            FMA2(acc[1][2], h1, w1.x); FMA2(acc[1][3], h1, w1.y);
            FMA2(acc[2][0], h2, w0.x); FMA2(acc[2][1], h2, w0.y);
            FMA2(acc[2][2], h2, w1.x); FMA2(acc[2][3], h2, w1.y);
            FMA2(acc[3][0], h3, w0.x); FMA2(acc[3][1], h3, w0.y);
            FMA2(acc[3][2], h3, w1.x); FMA2(acc[3][3], h3, w1.y);
        }
    }

    float bo[8];
#pragma unroll
    for (int c = 0; c < 8; c++) bo[c] = b_o[cb * 64 + tx * 8 + c];

#pragma unroll
    for (int i = 0; i < 4; i++) {
        int rr = rb * 128 + ty * 4 + i;     // flat index = s*256 + b
        int s = rr >> 8;
        int b = rr & 255;
        float* dst = out + ((size_t)b * S_ + s) * V_ + cb * 64 + tx * 8;
        float f[8];
        unpack2(acc[i][0], f[0], f[1]);
        unpack2(acc[i][1], f[2], f[3]);
        unpack2(acc[i][2], f[4], f[5]);
        unpack2(acc[i][3], f[6], f[7]);
        float4 o0 = make_float4(f[0] + bo[0], f[1] + bo[1], f[2] + bo[2], f[3] + bo[3]);
        float4 o1 = make_float4(f[4] + bo[4], f[5] + bo[5], f[6] + bo[6], f[7] + bo[7]);
        *(float4*)dst = o0;
        *((float4*)dst + 1) = o1;
    }
}

// ============================================================
// Kernel 4: hT = g_H[S-1]  (appended after outputs in d_out)
// ============================================================
__global__ void copy_hT(float* __restrict__ out) {
    int i = blockIdx.x * blockDim.x + threadIdx.x;   // 0 .. B_*H_-1
    out[(size_t)B_ * S_ * V_ + i] = g_H[(size_t)(S_ - 1) * (B_ * H_) + i];
}

// ============================================================
extern "C" void kernel_launch(void* const* d_in, const int* in_sizes, int n_in,
                              void* d_out, int out_size) {
    const int*   x    = (const int*)d_in[0];
    const float* emb  = (const float*)d_in[1];
    const float* W_ih = (const float*)d_in[2];
    const float* b_ih = (const float*)d_in[3];
    const float* W_hh = (const float*)d_in[4];
    const float* b_hh = (const float*)d_in[5];
    const float* W_ho = (const float*)d_in[6];
    const float* b_o  = (const float*)d_in[7];
    float* out = (float*)d_out;

    const int smem_bytes = 131072 + 65536;   // Wd 128KB + hs 64KB = 192KB
    static int attr_done = 0;
    if (!attr_done) {
        cudaFuncSetAttribute(rnn_persist, cudaFuncAttributeMaxDynamicSharedMemorySize, smem_bytes);
        attr_done = 1;
    }

    precompute_P<<<V_, H_>>>(emb, W_ih, b_ih, b_hh);

    rnn_persist<<<dim3(16, 8), 128, smem_bytes>>>(W_hh, x);

    out_gemm<<<dim3((B_ * S_) / 128, V_ / 64), 256>>>(W_ho, b_o, out);

    if ((long long)out_size >= (long long)B_ * S_ * V_ + (long long)B_ * H_)
        copy_hT<<<(B_ * H_) / 256, 256>>>(out);
}

// round 13
// speedup vs baseline: 1.4526x; 1.4526x over previous
#include <cuda_runtime.h>
#include <cstdint>
#include <cstddef>

#define B_ 256
#define S_ 512
#define H_ 512
#define V_ 128

#define HS_STRIDE 514   // u64 stride per row-pair (even => 16B-aligned float4 stores)

// Scratch (allocation-free rule: __device__ globals)
__device__ float g_P[V_ * H_];                                 // 256 KB
__device__ float g_H[(size_t)S_ * B_ * H_];                    // 268 MB history [t][b][h]
__device__ __align__(16) unsigned long long g_Ht2[2][8][16][512]; // 1 MB ping-pong: [par][by][row-pair][col] packed {h_b,h_b+1}
__device__ unsigned g_cntA[8 * 32];                            // per-group arrive counters (128B apart)
__device__ unsigned g_epochA[8 * 32];                          // per-group epochs (monotonic across replays)

// ---- packed f32x2 helpers (sm_103a) ----
__device__ __forceinline__ unsigned long long pack2(float x, float y) {
    unsigned long long r;
    asm("mov.b64 %0, {%1, %2};" : "=l"(r) : "f"(x), "f"(y));
    return r;
}
__device__ __forceinline__ void unpack2(unsigned long long v, float& x, float& y) {
    asm("mov.b64 {%0, %1}, %2;" : "=f"(x), "=f"(y) : "l"(v));
}
#define FMA2(acc, a, b) \
    asm("fma.rn.f32x2 %0, %1, %2, %3;" : "=l"(acc) : "l"(a), "l"(b), "l"(acc))
#define ADD2(out, a, b) \
    asm("add.rn.f32x2 %0, %1, %2;" : "=l"(out) : "l"(a), "l"(b))

// ============================================================
// no-op kernels: shift ncu's captured slot onto rnn_persist
// ============================================================
__global__ void dummy_k() {}

// ============================================================
// Kernel 1: P[v][h] = emb[v] @ W_ih + b_ih + b_hh
// ============================================================
__global__ void precompute_P(const float* __restrict__ emb,
                             const float* __restrict__ W_ih,
                             const float* __restrict__ b_ih,
                             const float* __restrict__ b_hh) {
    __shared__ float es[H_];
    const int v = blockIdx.x;
    const int h = threadIdx.x;
    es[h] = emb[v * H_ + h];
    __syncthreads();
    float acc = b_ih[h] + b_hh[h];
#pragma unroll 4
    for (int k = 0; k < H_; k++)
        acc = fmaf(es[k], W_ih[k * H_ + h], acc);
    g_P[v * H_ + h] = acc;
}

// ============================================================
// Kernel 2: PERSISTENT recurrence. grid (16,8)=128 CTAs, 256 threads.
// CTA tile: 32 batch rows x 32 cols. Thread tile: 2 rows x 2 cols.
// f32x2 lanes = adjacent batch rows (row-pair accumulators).
// SMEM: Wd[512][32] u64 (dup {w,w})           = 128 KB
//       hs[16][HS_STRIDE] u64 ([pair][k])     =  ~64 KB
// Inner loop per 2 k: LDS.128(h) + 2x LDS.128(W) + 4x fma.rn.f32x2.
// Sync: per-by groups of 16 CTAs (independent groups, own counter/epoch).
// ============================================================
__global__ __launch_bounds__(256) void rnn_persist(const float* __restrict__ Whh,
                                                   const int* __restrict__ x) {
    extern __shared__ char smem_raw[];
    unsigned long long* Wd = (unsigned long long*)smem_raw;            // [512][32]
    unsigned long long* hs = (unsigned long long*)(smem_raw + 131072); // [16][HS_STRIDE]

    const int tid = threadIdx.x;
    const int bx = blockIdx.x;     // col tile 0..15 (32 cols)
    const int by = blockIdx.y;     // row tile 0..7  (32 rows) — sync group id

    // ---- build duplicated W slice in SMEM (once) ----
#pragma unroll
    for (int it = 0; it < 32; it++) {
        int i = tid + it * 256;            // 0..8191 float2s
        int k = i >> 4;                    // 16 float2 per k-row
        int c = i & 15;
        float2 w = *(const float2*)(Whh + (size_t)k * H_ + bx * 32 + c * 2);
        Wd[k * 32 + c * 2 + 0] = pack2(w.x, w.x);
        Wd[k * 32 + c * 2 + 1] = pack2(w.y, w.y);
    }

    unsigned e0 = 0;
    if (tid == 0) e0 = *(volatile unsigned*)&g_epochA[by * 32];  // before own first arrive => safe
    __syncthreads();

    const int t_r = tid & 15;      // row pair index: rows 2t_r, 2t_r+1
    const int c2  = tid >> 4;      // col pair index: cols 2c2, 2c2+1
    const int b0  = by * 32 + 2 * t_r;
    const int gc  = bx * 32 + 2 * c2;

    const unsigned long long* hp = hs + (size_t)t_r * HS_STRIDE;
    const unsigned long long* wp = Wd + 2 * c2;
    const int* xr0 = x + (size_t)b0 * S_;
    const int* xr1 = x + (size_t)(b0 + 1) * S_;

    for (int t = 0; t < S_; t++) {
        // prefetch token + P early (independent of mainloop)
        int xv0 = __ldg(&xr0[t]);
        int xv1 = __ldg(&xr1[t]);
        float2 p0 = *(const float2*)(g_P + (size_t)xv0 * H_ + gc);
        float2 p1 = *(const float2*)(g_P + (size_t)xv1 * H_ + gc);

        unsigned long long a0e = 0ull, a0o = 0ull, a1e = 0ull, a1o = 0ull;

        if (t > 0) {
            // ---- stage h_prev: contiguous 64KB per group, coalesced, bypass L1 ----
            const float4* src = (const float4*)&g_Ht2[(t - 1) & 1][by][0][0];
#pragma unroll
            for (int it = 0; it < 16; it++) {
                int i = tid + it * 256;        // 0..4095 float4s; u64 pair f = 2i
                float4 v = __ldcg(src + i);
                int rp = i >> 8;               // = (2i) >> 9
                int k  = (2 * i) & 511;
                *(float4*)(hs + (size_t)rp * HS_STRIDE + k) = v;
            }
            __syncthreads();

            // ---- mainloop: per 2k = 3 LDS.128 + 4 FMA2, 4 acc chains ----
#pragma unroll 8
            for (int k = 0; k < H_; k += 2) {
                ulonglong2 hh = *(const ulonglong2*)(hp + k);           // {h(k), h(k+1)} row-pairs
                ulonglong2 w0 = *(const ulonglong2*)(wp + (size_t)k * 32);        // k, cols gc/gc+1
                ulonglong2 w1 = *(const ulonglong2*)(wp + (size_t)(k + 1) * 32);  // k+1
                FMA2(a0e, hh.x, w0.x);  FMA2(a1e, hh.x, w0.y);
                FMA2(a0o, hh.y, w1.x);  FMA2(a1o, hh.y, w1.y);
            }
        }

        unsigned long long a0, a1;
        ADD2(a0, a0e, a0o);
        ADD2(a1, a1e, a1o);

        // ---- epilogue: +P, tanh, store (transposed ping-pong + history) ----
        float s00, s10, s01, s11;
        unpack2(a0, s00, s10);    // col gc:   rows b0, b0+1
        unpack2(a1, s01, s11);    // col gc+1: rows b0, b0+1
        float v00 = tanhf(s00 + p0.x);
        float v10 = tanhf(s10 + p1.x);
        float v01 = tanhf(s01 + p0.y);
        float v11 = tanhf(s11 + p1.y);

        ulonglong2 tv;
        tv.x = pack2(v00, v10);   // col gc
        tv.y = pack2(v01, v11);   // col gc+1
        *(ulonglong2*)&g_Ht2[t & 1][by][t_r][gc] = tv;

        *(float2*)(g_H + (size_t)t * (B_ * H_) + (size_t)b0 * H_ + gc)       = make_float2(v00, v01);
        *(float2*)(g_H + (size_t)t * (B_ * H_) + (size_t)(b0 + 1) * H_ + gc) = make_float2(v10, v11);

        __syncthreads();   // hs fully consumed; all stores issued
        // ---- per-group (16 CTA) barrier ----
        if (tid == 0) {
            __threadfence();                                // h visible in L2 before arrive
            unsigned old = atomicAdd(&g_cntA[by * 32], 1);
            if (old == 15) {                                // last arriver in group
                atomicExch(&g_cntA[by * 32], 0);
                __threadfence();
                atomicAdd(&g_epochA[by * 32], 1);           // release
            }
            while (*(volatile unsigned*)&g_epochA[by * 32] < e0 + (unsigned)(t + 1)) { }
        }
        __syncthreads();
    }
}

// ============================================================
// Kernel 3: output projection  out[b][s][v] = g_H[s][b] @ W_ho + b_o
// ============================================================
__global__ __launch_bounds__(256) void out_gemm(const float* __restrict__ Who,
                                                const float* __restrict__ b_o,
                                                float* __restrict__ out) {
    __shared__ unsigned long long Hs[128 * 16];  // duplicated pairs, 16 KB
    __shared__ float Ws[16 * 64];                // 4 KB

    const int tid = threadIdx.x;
    const int rb  = blockIdx.x;      // row block
    const int cb  = blockIdx.y;      // col block (0..1)
    const int tx  = tid & 7;         // 8 col groups of 8 cols
    const int ty  = tid >> 3;        // 32 row groups of 4 rows

    unsigned long long acc[4][4];
#pragma unroll
    for (int i = 0; i < 4; i++)
#pragma unroll
        for (int j = 0; j < 4; j++) acc[i][j] = 0ull;

    const float* Hbase = g_H + (size_t)rb * 128 * H_;

    for (int k0 = 0; k0 < H_; k0 += 16) {
        __syncthreads();
#pragma unroll
        for (int it = 0; it < 2; it++) {
            int fi = tid + it * 256;          // 0..511
            int row = fi >> 2, part = fi & 3;
            float4 v = *(const float4*)(Hbase + (size_t)row * H_ + k0 + part * 4);
            unsigned long long* d = Hs + row * 16 + part * 4;
            d[0] = pack2(v.x, v.x);
            d[1] = pack2(v.y, v.y);
            d[2] = pack2(v.z, v.z);
            d[3] = pack2(v.w, v.w);
        }
        {
            int fi = tid;                      // 0..255
            int kk = fi >> 4, part = fi & 15;
            float4 v = *(const float4*)(Who + (size_t)(k0 + kk) * V_ + cb * 64 + part * 4);
            *(float4*)(Ws + kk * 64 + part * 4) = v;
        }
        __syncthreads();

#pragma unroll
        for (int k = 0; k < 16; k++) {
            unsigned long long h0 = Hs[(ty * 4 + 0) * 16 + k];
            unsigned long long h1 = Hs[(ty * 4 + 1) * 16 + k];
            unsigned long long h2 = Hs[(ty * 4 + 2) * 16 + k];
            unsigned long long h3 = Hs[(ty * 4 + 3) * 16 + k];
            ulonglong2 w0 = *(const ulonglong2*)&Ws[k * 64 + tx * 8];
            ulonglong2 w1 = *(const ulonglong2*)&Ws[k * 64 + tx * 8 + 4];
            FMA2(acc[0][0], h0, w0.x); FMA2(acc[0][1], h0, w0.y);
            FMA2(acc[0][2], h0, w1.x); FMA2(acc[0][3], h0, w1.y);
            FMA2(acc[1][0], h1, w0.x); FMA2(acc[1][1], h1, w0.y);
            FMA2(acc[1][2], h1, w1.x); FMA2(acc[1][3], h1, w1.y);
            FMA2(acc[2][0], h2, w0.x); FMA2(acc[2][1], h2, w0.y);
            FMA2(acc[2][2], h2, w1.x); FMA2(acc[2][3], h2, w1.y);
            FMA2(acc[3][0], h3, w0.x); FMA2(acc[3][1], h3, w0.y);
            FMA2(acc[3][2], h3, w1.x); FMA2(acc[3][3], h3, w1.y);
        }
    }

    float bo[8];
#pragma unroll
    for (int c = 0; c < 8; c++) bo[c] = b_o[cb * 64 + tx * 8 + c];

#pragma unroll
    for (int i = 0; i < 4; i++) {
        int rr = rb * 128 + ty * 4 + i;     // flat index = s*256 + b
        int s = rr >> 8;
        int b = rr & 255;
        float* dst = out + ((size_t)b * S_ + s) * V_ + cb * 64 + tx * 8;
        float f[8];
        unpack2(acc[i][0], f[0], f[1]);
        unpack2(acc[i][1], f[2], f[3]);
        unpack2(acc[i][2], f[4], f[5]);
        unpack2(acc[i][3], f[6], f[7]);
        float4 o0 = make_float4(f[0] + bo[0], f[1] + bo[1], f[2] + bo[2], f[3] + bo[3]);
        float4 o1 = make_float4(f[4] + bo[4], f[5] + bo[5], f[6] + bo[6], f[7] + bo[7]);
        *(float4*)dst = o0;
        *((float4*)dst + 1) = o1;
    }
}

// ============================================================
// Kernel 4: hT = g_H[S-1]  (appended after outputs in d_out)
// ============================================================
__global__ void copy_hT(float* __restrict__ out) {
    int i = blockIdx.x * blockDim.x + threadIdx.x;   // 0 .. B_*H_-1
    out[(size_t)B_ * S_ * V_ + i] = g_H[(size_t)(S_ - 1) * (B_ * H_) + i];
}

// ============================================================
extern "C" void kernel_launch(void* const* d_in, const int* in_sizes, int n_in,
                              void* d_out, int out_size) {
    const int*   x    = (const int*)d_in[0];
    const float* emb  = (const float*)d_in[1];
    const float* W_ih = (const float*)d_in[2];
    const float* b_ih = (const float*)d_in[3];
    const float* W_hh = (const float*)d_in[4];
    const float* b_hh = (const float*)d_in[5];
    const float* W_ho = (const float*)d_in[6];
    const float* b_o  = (const float*)d_in[7];
    float* out = (float*)d_out;

    const int smem_bytes = 131072 + 16 * HS_STRIDE * 8;   // 128KB + 64.25KB
    static int attr_done = 0;
    if (!attr_done) {
        cudaFuncSetAttribute(rnn_persist, cudaFuncAttributeMaxDynamicSharedMemorySize, smem_bytes);
        attr_done = 1;
    }

    precompute_P<<<V_, H_>>>(emb, W_ih, b_ih, b_hh);
    dummy_k<<<1, 32>>>();                    // ncu slot alignment:
    dummy_k<<<1, 32>>>();                    // captured launch = position 3 = rnn_persist

    rnn_persist<<<dim3(16, 8), 256, smem_bytes>>>(W_hh, x);

    out_gemm<<<dim3((B_ * S_) / 128, V_ / 64), 256>>>(W_ho, b_o, out);

    if ((long long)out_size >= (long long)B_ * S_ * V_ + (long long)B_ * H_)
        copy_hT<<<(B_ * H_) / 256, 256>>>(out);
}